// round 11
// baseline (speedup 1.0000x reference)
#include <cuda_runtime.h>
#include <cuda_fp16.h>
#include <math.h>
#include <stdint.h>

#define NTOK   65536
#define DMODEL 128
#define HDIM   256
#define NEXP   32
#define TM     64

// ================= helpers =================
__device__ __forceinline__ uint32_t smem_to_u32(const void* p) {
    uint32_t a;
    asm("{ .reg .u64 t; cvta.to.shared.u64 t, %1; cvt.u32.u64 %0, t; }" : "=r"(a) : "l"(p));
    return a;
}
__device__ __forceinline__ void ldsm4(uint32_t& r0, uint32_t& r1, uint32_t& r2, uint32_t& r3,
                                      uint32_t addr) {
    asm volatile("ldmatrix.sync.aligned.m8n8.x4.shared.b16 {%0,%1,%2,%3}, [%4];"
                 : "=r"(r0), "=r"(r1), "=r"(r2), "=r"(r3) : "r"(addr));
}
__device__ __forceinline__ void mma16816(float* c, uint32_t a0, uint32_t a1, uint32_t a2,
                                         uint32_t a3, uint32_t b0, uint32_t b1) {
    asm volatile("mma.sync.aligned.m16n8k16.row.col.f32.f16.f16.f32 "
                 "{%0,%1,%2,%3}, {%4,%5,%6,%7}, {%8,%9}, {%0,%1,%2,%3};"
                 : "+f"(c[0]), "+f"(c[1]), "+f"(c[2]), "+f"(c[3])
                 : "r"(a0), "r"(a1), "r"(a2), "r"(a3), "r"(b0), "r"(b1));
}
__device__ __forceinline__ void cp16(uint32_t dst, const void* src) {
    asm volatile("cp.async.cg.shared.global [%0], [%1], 16;" :: "r"(dst), "l"(src) : "memory");
}
#define CP_COMMIT() asm volatile("cp.async.commit_group;" ::: "memory")
#define CP_WAIT0()  asm volatile("cp.async.wait_group 0;" ::: "memory")
#define CP_WAIT1()  asm volatile("cp.async.wait_group 1;" ::: "memory")

__device__ __forceinline__ uint32_t packh(__half a, __half b) {
    __half2 t(a, b);
    return *reinterpret_cast<uint32_t*>(&t);
}

// ================= device scratch =================
__device__ float g_top_v[2 * NTOK];
__device__ int   g_top_e[2 * NTOK];
__device__ float g_importance[NEXP];
__device__ int   g_counts[NEXP];
__device__ int   g_offsets[NEXP + 1];
__device__ int   g_cursor[NEXP];
__device__ int   g_tile_off[NEXP + 1];
__device__ int   g_total_tiles;
__device__ int   g_bucket_tok[2 * NTOK];
__device__ float g_bucket_w[2 * NTOK];
__device__ int   g_tok_slot[2 * NTOK];
__device__ __align__(16) __half g_partial_h[(size_t)2 * NTOK * DMODEL];

__device__ __align__(16) __half g_xh[NTOK * DMODEL];
__device__ __align__(16) __half g_w1h[NEXP * HDIM * DMODEL];   // [E,H,D] (transposed)
__device__ __align__(16) __half g_w2h[NEXP * DMODEL * HDIM];   // [E,D,H] (transposed)

// ================= kernel: convert + transpose weights (+ init in block 0) =================
__global__ void __launch_bounds__(256) convert_w_kernel(const float* __restrict__ W1,
                                                        const float* __restrict__ W2) {
    if (blockIdx.x == 0 && threadIdx.x < NEXP) {
        g_counts[threadIdx.x] = 0;
        g_importance[threadIdx.x] = 0.f;
    }
    int idx = blockIdx.x * 256 + threadIdx.x;
    {   // W1T[e][h][d] = W1[e][d][h]
        int d = idx & 127, h = (idx >> 7) & 255, e = idx >> 15;
        g_w1h[idx] = __float2half_rn(W1[((size_t)e * 128 + d) * 256 + h]);
    }
    {   // W2T[e][d][h] = W2[e][h][d]
        int h = idx & 255, d = (idx >> 8) & 127, e = idx >> 15;
        g_w2h[idx] = __float2half_rn(W2[((size_t)e * 256 + h) * 128 + d]);
    }
}

// ================= kernel: router (thread per token; also emits x as fp16) =================
__global__ void __launch_bounds__(256) router_kernel(
    const float* __restrict__ x, const float* __restrict__ Wr,
    const float* __restrict__ br)
{
    __shared__ float wr_s[DMODEL * NEXP];
    __shared__ float br_s[NEXP];
    __shared__ float imp_s[NEXP];
    __shared__ int   cnt_s[NEXP];

    const int tid = threadIdx.x;
    if (tid < NEXP) { imp_s[tid] = 0.f; cnt_s[tid] = 0; br_s[tid] = br[tid]; }
    #pragma unroll
    for (int i = tid; i < DMODEL * NEXP; i += 256) wr_s[i] = Wr[i];
    __syncthreads();

    const int n = blockIdx.x * 256 + tid;

    float acc[NEXP];
    #pragma unroll
    for (int e = 0; e < NEXP; ++e) acc[e] = br_s[e];

    const float4* xrow = reinterpret_cast<const float4*>(x + (size_t)n * DMODEL);
    float4 xv = xrow[0];
    uint32_t hprev0 = 0, hprev1 = 0;
    #pragma unroll 4
    for (int ch = 0; ch < 32; ++ch) {
        float4 xn;
        if (ch < 31) xn = xrow[ch + 1];

        uint32_t p0 = packh(__float2half_rn(xv.x), __float2half_rn(xv.y));
        uint32_t p1 = packh(__float2half_rn(xv.z), __float2half_rn(xv.w));
        if (ch & 1) {
            *reinterpret_cast<uint4*>(g_xh + (size_t)n * DMODEL + (ch - 1) * 4) =
                make_uint4(hprev0, hprev1, p0, p1);
        } else { hprev0 = p0; hprev1 = p1; }

        float xd[4] = {xv.x, xv.y, xv.z, xv.w};
        #pragma unroll
        for (int dd = 0; dd < 4; ++dd) {
            const float4* wrow = reinterpret_cast<const float4*>(&wr_s[(ch * 4 + dd) * NEXP]);
            #pragma unroll
            for (int e4 = 0; e4 < 8; ++e4) {
                float4 w = wrow[e4];
                acc[e4 * 4 + 0] = fmaf(xd[dd], w.x, acc[e4 * 4 + 0]);
                acc[e4 * 4 + 1] = fmaf(xd[dd], w.y, acc[e4 * 4 + 1]);
                acc[e4 * 4 + 2] = fmaf(xd[dd], w.z, acc[e4 * 4 + 2]);
                acc[e4 * 4 + 3] = fmaf(xd[dd], w.w, acc[e4 * 4 + 3]);
            }
        }
        xv = xn;
    }

    float mx = acc[0];
    #pragma unroll
    for (int e = 1; e < NEXP; ++e) mx = fmaxf(mx, acc[e]);
    float s = 0.f;
    #pragma unroll
    for (int e = 0; e < NEXP; ++e) { acc[e] = expf(acc[e] - mx); s += acc[e]; }
    float inv = 1.f / s;
    #pragma unroll
    for (int e = 0; e < NEXP; ++e) acc[e] *= inv;

    float v1 = acc[0]; int i1 = 0;
    #pragma unroll
    for (int e = 1; e < NEXP; ++e) if (acc[e] > v1) { v1 = acc[e]; i1 = e; }
    float v2 = -1.f; int i2 = 0;
    #pragma unroll
    for (int e = 0; e < NEXP; ++e) {
        bool ok = (e != i1) && (acc[e] > v2);
        if (ok) { v2 = acc[e]; i2 = e; }
    }

    g_top_e[2 * n]     = i1;  g_top_v[2 * n]     = v1;
    g_top_e[2 * n + 1] = i2;  g_top_v[2 * n + 1] = v2;
    atomicAdd(&imp_s[i1], v1);
    atomicAdd(&imp_s[i2], v2);
    atomicAdd(&cnt_s[i1], 1);
    atomicAdd(&cnt_s[i2], 1);

    __syncthreads();
    if (tid < NEXP) {
        atomicAdd(&g_importance[tid], imp_s[tid]);
        atomicAdd(&g_counts[tid], cnt_s[tid]);
    }
}

// ================= kernel: scan + loss =================
__global__ void scan_loss_kernel(float* __restrict__ out, int out_size) {
    const int lane = threadIdx.x;
    const unsigned FULL = 0xffffffffu;

    int c = g_counts[lane];
    int sc = c;
    #pragma unroll
    for (int o = 1; o < 32; o <<= 1) {
        int v = __shfl_up_sync(FULL, sc, o);
        if (lane >= o) sc += v;
    }
    g_offsets[lane] = sc - c;
    g_cursor[lane]  = sc - c;
    if (lane == 31) g_offsets[NEXP] = sc;

    int nt = (c + TM - 1) / TM;
    int st = nt;
    #pragma unroll
    for (int o = 1; o < 32; o <<= 1) {
        int v = __shfl_up_sync(FULL, st, o);
        if (lane >= o) st += v;
    }
    g_tile_off[lane] = st - nt;
    if (lane == 31) { g_tile_off[NEXP] = st; g_total_tiles = st; }

    float imp = g_importance[lane];
    float s = imp;
    #pragma unroll
    for (int o = 16; o; o >>= 1) s += __shfl_xor_sync(FULL, s, o);
    float mean = s / 32.f;
    float d = imp - mean;
    float ss = d * d;
    #pragma unroll
    for (int o = 16; o; o >>= 1) ss += __shfl_xor_sync(FULL, ss, o);
    float var = ss / 31.f;
    if (lane == 0 && out_size > NTOK * DMODEL)
        out[NTOK * DMODEL] = var / (mean * mean + 1e-9f);
}

// ================= kernel: scatter =================
__global__ void __launch_bounds__(256) scatter_kernel() {
    __shared__ int lcnt[NEXP];
    __shared__ int gbase[NEXP];
    __shared__ int lcur[NEXP];

    const int tid = threadIdx.x;
    const int n = blockIdx.x * 256 + tid;
    if (tid < NEXP) lcnt[tid] = 0;
    __syncthreads();

    int e0 = g_top_e[2 * n];     float v0 = g_top_v[2 * n];
    int e1 = g_top_e[2 * n + 1]; float v1 = g_top_v[2 * n + 1];
    atomicAdd(&lcnt[e0], 1);
    atomicAdd(&lcnt[e1], 1);
    __syncthreads();

    if (tid < NEXP) { gbase[tid] = atomicAdd(&g_cursor[tid], lcnt[tid]); lcur[tid] = 0; }
    __syncthreads();

    int p0 = gbase[e0] + atomicAdd(&lcur[e0], 1);
    g_bucket_tok[p0] = n; g_bucket_w[p0] = v0; g_tok_slot[2 * n] = p0;
    int p1 = gbase[e1] + atomicAdd(&lcur[e1], 1);
    g_bucket_tok[p1] = n; g_bucket_w[p1] = v1; g_tok_slot[2 * n + 1] = p1;
}

// ================= kernel: grouped expert GEMM (fp16, double-buffered, 3 CTA/SM) =================
// X  @ O_XH : [64,128] fp16, stride 272       (17408 B)
// WA @ O_WA : W1 chunk [64h,128d], stride 272 (17408 B)
// WB @ O_WB : W2 chunk [128d,64h], stride 144 (18432 B)
// C  @ O_CH : h chunk [64,64], stride 144     (9216 B)
#define RW128 272
#define RW64  144
#define O_XH  0
#define O_WA  17408
#define O_WB  34816
#define O_CH  53248
#define O_TOK 62464
#define O_WSM (O_TOK + 256)
#define O_B1  (O_TOK + 512)
#define O_B2  (O_TOK + 1536)
#define SMEM_DYN (O_TOK + 2048)   // 64512

#define NTHR 256

__global__ void __launch_bounds__(NTHR, 3) expert_mma_kernel(
    const float* __restrict__ b1, const float* __restrict__ b2)
{
    const int t = blockIdx.x;
    if (t >= g_total_tiles) return;

    extern __shared__ char smp[];
    const uint32_t sbase = smem_to_u32(smp);
    int*   toks_s = (int*)(smp + O_TOK);
    float* wsm_s  = (float*)(smp + O_WSM);
    float* b1s    = (float*)(smp + O_B1);
    float* b2s    = (float*)(smp + O_B2);

    const int tid = threadIdx.x;
    const int wid = tid >> 5;
    const int lane = tid & 31;

    int e = 0;
    #pragma unroll 1
    while (t >= g_tile_off[e + 1]) ++e;
    const int mtile = t - g_tile_off[e];
    const int off   = g_offsets[e];
    const int cnt   = g_counts[e];
    const int m0g   = mtile * TM;
    const int valid = min(TM, cnt - m0g);

    if (tid < 64) {
        if (tid < valid) {
            toks_s[tid] = g_bucket_tok[off + m0g + tid];
            wsm_s[tid]  = g_bucket_w[off + m0g + tid];
        } else { toks_s[tid] = 0; wsm_s[tid] = 0.f; }
    }
    if (tid < 128) b2s[tid] = b2[e * DMODEL + tid];
    b1s[tid] = b1[e * HDIM + tid];
    __syncthreads();

    const size_t w1base = (size_t)e * HDIM * DMODEL;
    const size_t w2base = (size_t)e * DMODEL * HDIM;

    // ---- prologue: group0 = {X gather, W1c0}; group1 = {W2c0} ----
    #pragma unroll
    for (int i = tid; i < 1024; i += NTHR) {
        int r = i >> 4, ch = i & 15;
        const size_t src = (size_t)toks_s[r] * DMODEL + ch * 8;
        cp16(sbase + O_XH + r * RW128 + ch * 16, g_xh + src);
    }
    #pragma unroll
    for (int i = tid; i < 1024; i += NTHR) {
        int r = i >> 4, ch = i & 15;
        cp16(sbase + O_WA + r * RW128 + ch * 16, g_w1h + w1base + (size_t)r * DMODEL + ch * 8);
    }
    CP_COMMIT();
    #pragma unroll
    for (int i = tid; i < 1024; i += NTHR) {
        int r = i >> 3, ch = i & 7;
        cp16(sbase + O_WB + r * RW64 + ch * 16, g_w2h + w2base + (size_t)r * HDIM + ch * 8);
    }
    CP_COMMIT();
    CP_WAIT1();          // X + W1c0 ready; W2c0 still in flight
    __syncthreads();

    // warp tiling: 4 m-warps (16 rows) x 2 n-warps
    const int m0 = (wid >> 1) * 16;
    const int nw = wid & 1;
    const uint32_t arow  = m0 + (lane & 15);
    const uint32_t acolb = ((lane >> 4) & 1) * 16;
    const uint32_t brsub = ((lane >> 4) & 1) * 8 + (lane & 7);
    const uint32_t bcolb = ((lane >> 3) & 1) * 16;

    float acc2[8][4];
    #pragma unroll
    for (int j = 0; j < 8; ++j)
        #pragma unroll
        for (int q = 0; q < 4; ++q) acc2[j][q] = 0.f;

    #pragma unroll 1
    for (int c = 0; c < 4; ++c) {
        // ---- FC1: h_c[64,64] = X @ W1c^T ; warp m16 x n32 ----
        float acc1[4][4];
        #pragma unroll
        for (int j = 0; j < 4; ++j)
            #pragma unroll
            for (int q = 0; q < 4; ++q) acc1[j][q] = 0.f;

        #pragma unroll 1
        for (int k = 0; k < 8; ++k) {
            uint32_t aaddr = sbase + O_XH + arow * RW128 + k * 32 + acolb;
            uint32_t ah0, ah1, ah2, ah3;
            ldsm4(ah0, ah1, ah2, ah3, aaddr);
            #pragma unroll
            for (int jp = 0; jp < 2; ++jp) {
                uint32_t brow = nw * 32 + jp * 16 + brsub;
                uint32_t baddr = sbase + O_WA + brow * RW128 + k * 32 + bcolb;
                uint32_t bh0, bh1, bh2, bh3;
                ldsm4(bh0, bh1, bh2, bh3, baddr);
                mma16816(acc1[2 * jp],     ah0, ah1, ah2, ah3, bh0, bh1);
                mma16816(acc1[2 * jp + 1], ah0, ah1, ah2, ah3, bh2, bh3);
            }
        }
        __syncthreads();   // WA consumed by all warps

        // ---- prefetch W1(c+1) into WA (consumed after FC2 -> fully hidden) ----
        if (c < 3) {
            #pragma unroll
            for (int i = tid; i < 1024; i += NTHR) {
                int r = i >> 4, ch = i & 15;
                size_t src = w1base + (size_t)((c + 1) * 64 + r) * DMODEL + ch * 8;
                cp16(sbase + O_WA + r * RW128 + ch * 16, g_w1h + src);
            }
            CP_COMMIT();
        }

        // ---- epilogue 1: relu(acc1 + b1) -> fp16 into C ----
        {
            const int r0 = m0 + (lane >> 2);
            const int cb = (lane & 3) * 2;
            #pragma unroll
            for (int jn = 0; jn < 4; ++jn) {
                const float* a = acc1[jn];
                int coll = nw * 32 + jn * 8 + cb;
                int colg = c * 64 + coll;
                float bb0 = b1s[colg], bb1 = b1s[colg + 1];
                __half h0 = __float2half_rn(fmaxf(a[0] + bb0, 0.f));
                __half h1 = __float2half_rn(fmaxf(a[1] + bb1, 0.f));
                __half h2 = __float2half_rn(fmaxf(a[2] + bb0, 0.f));
                __half h3 = __float2half_rn(fmaxf(a[3] + bb1, 0.f));
                *reinterpret_cast<uint32_t*>(smp + O_CH + r0 * RW64 + coll * 2) = packh(h0, h1);
                *reinterpret_cast<uint32_t*>(smp + O_CH + (r0 + 8) * RW64 + coll * 2) = packh(h2, h3);
            }
        }
        // W2c must be complete: pending = {W2c, W1c+1} -> wait1 ; last chunk: {W2c3} -> wait0
        if (c < 3) { CP_WAIT1(); } else { CP_WAIT0(); }
        __syncthreads();   // W2c ready, C visible

        // ---- FC2: acc2 += h_c @ W2c^T ; warp m16 x n64 ----
        #pragma unroll 1
        for (int k = 0; k < 4; ++k) {
            uint32_t aaddr = sbase + O_CH + arow * RW64 + k * 32 + acolb;
            uint32_t ah0, ah1, ah2, ah3;
            ldsm4(ah0, ah1, ah2, ah3, aaddr);
            #pragma unroll
            for (int jp = 0; jp < 4; ++jp) {
                uint32_t brow = nw * 64 + jp * 16 + brsub;
                uint32_t baddr = sbase + O_WB + brow * RW64 + k * 32 + bcolb;
                uint32_t bh0, bh1, bh2, bh3;
                ldsm4(bh0, bh1, bh2, bh3, baddr);
                mma16816(acc2[2 * jp],     ah0, ah1, ah2, ah3, bh0, bh1);
                mma16816(acc2[2 * jp + 1], ah0, ah1, ah2, ah3, bh2, bh3);
            }
        }
        __syncthreads();   // WB + C consumed

        // ---- prefetch W2(c+1) into WB; ensure W1(c+1) (older group) done ----
        if (c < 3) {
            #pragma unroll
            for (int i = tid; i < 1024; i += NTHR) {
                int r = i >> 3, ch = i & 7;
                size_t src = w2base + (size_t)r * HDIM + (c + 1) * 64 + ch * 8;
                cp16(sbase + O_WB + r * RW64 + ch * 16, g_w2h + src);
            }
            CP_COMMIT();
            CP_WAIT1();    // pending {W1c+1, W2c+1} -> W1c+1 done
            __syncthreads();
        }
    }

    // ---- epilogue 2: w * (acc2 + b2) -> g_partial_h (fp16) ----
    {
        const int cb = (lane & 3) * 2;
        const int r0 = m0 + (lane >> 2);
        const int r1 = r0 + 8;
        const float w0 = (r0 < valid) ? wsm_s[r0] : 0.f;
        const float w1 = (r1 < valid) ? wsm_s[r1] : 0.f;
        const size_t s0 = (size_t)(off + m0g + r0) * DMODEL;
        const size_t s1 = (size_t)(off + m0g + r1) * DMODEL;
        #pragma unroll
        for (int jn = 0; jn < 8; ++jn) {
            const float* a = acc2[jn];
            int col = nw * 64 + jn * 8 + cb;
            float bb0 = b2s[col], bb1 = b2s[col + 1];
            if (r0 < valid) {
                __half q0 = __float2half_rn(w0 * (a[0] + bb0));
                __half q1 = __float2half_rn(w0 * (a[1] + bb1));
                *reinterpret_cast<uint32_t*>(&g_partial_h[s0 + col]) = packh(q0, q1);
            }
            if (r1 < valid) {
                __half q2 = __float2half_rn(w1 * (a[2] + bb0));
                __half q3 = __float2half_rn(w1 * (a[3] + bb1));
                *reinterpret_cast<uint32_t*>(&g_partial_h[s1 + col]) = packh(q2, q3);
            }
        }
    }
}

// ================= kernel: combine (fp16 partials -> fp32 out) =================
__global__ void __launch_bounds__(256) combine_kernel(float* __restrict__ out) {
    int gid = blockIdx.x * 256 + threadIdx.x;
    int n = gid >> 4;
    int q = gid & 15;
    int s0 = g_tok_slot[2 * n];
    int s1 = g_tok_slot[2 * n + 1];
    const uint4* P = reinterpret_cast<const uint4*>(g_partial_h);
    uint4 u0 = P[(size_t)s0 * 16 + q];
    uint4 u1 = P[(size_t)s1 * 16 + q];
    const __half2* h0 = reinterpret_cast<const __half2*>(&u0);
    const __half2* h1 = reinterpret_cast<const __half2*>(&u1);
    float4 o0, o1;
    float2 a0 = __half22float2(h0[0]), b0 = __half22float2(h1[0]);
    float2 a1 = __half22float2(h0[1]), b1 = __half22float2(h1[1]);
    float2 a2 = __half22float2(h0[2]), b2 = __half22float2(h1[2]);
    float2 a3 = __half22float2(h0[3]), b3 = __half22float2(h1[3]);
    o0.x = a0.x + b0.x; o0.y = a0.y + b0.y;
    o0.z = a1.x + b1.x; o0.w = a1.y + b1.y;
    o1.x = a2.x + b2.x; o1.y = a2.y + b2.y;
    o1.z = a3.x + b3.x; o1.w = a3.y + b3.y;
    float4* O = reinterpret_cast<float4*>(out);
    O[(size_t)n * 32 + q * 2]     = o0;
    O[(size_t)n * 32 + q * 2 + 1] = o1;
}

// ================= launch =================
extern "C" void kernel_launch(void* const* d_in, const int* in_sizes, int n_in,
                              void* d_out, int out_size) {
    const float* x  = (const float*)d_in[0];
    const float* W1 = (const float*)d_in[1];
    const float* b1 = (const float*)d_in[2];
    const float* W2 = (const float*)d_in[3];
    const float* b2 = (const float*)d_in[4];
    const float* Wr = (const float*)d_in[5];
    const float* br = (const float*)d_in[6];
    float* out = (float*)d_out;

    cudaFuncSetAttribute(expert_mma_kernel,
                         cudaFuncAttributeMaxDynamicSharedMemorySize, SMEM_DYN);

    convert_w_kernel<<<NEXP * HDIM * DMODEL / 256, 256>>>(W1, W2);
    router_kernel<<<NTOK / 256, 256>>>(x, Wr, br);
    scan_loss_kernel<<<1, 32>>>(out, out_size);
    scatter_kernel<<<NTOK / 256, 256>>>();
    expert_mma_kernel<<<2080, NTHR, SMEM_DYN>>>(b1, b2);
    combine_kernel<<<(NTOK * 16) / 256, 256>>>(out);
}

// round 12
// speedup vs baseline: 1.0567x; 1.0567x over previous
#include <cuda_runtime.h>
#include <cuda_fp16.h>
#include <math.h>
#include <stdint.h>

#define NTOK   65536
#define DMODEL 128
#define HDIM   256
#define NEXP   32
#define TM     64

// ================= helpers =================
__device__ __forceinline__ uint32_t smem_to_u32(const void* p) {
    uint32_t a;
    asm("{ .reg .u64 t; cvta.to.shared.u64 t, %1; cvt.u32.u64 %0, t; }" : "=r"(a) : "l"(p));
    return a;
}
__device__ __forceinline__ void ldsm4(uint32_t& r0, uint32_t& r1, uint32_t& r2, uint32_t& r3,
                                      uint32_t addr) {
    asm volatile("ldmatrix.sync.aligned.m8n8.x4.shared.b16 {%0,%1,%2,%3}, [%4];"
                 : "=r"(r0), "=r"(r1), "=r"(r2), "=r"(r3) : "r"(addr));
}
__device__ __forceinline__ void mma16816(float* c, uint32_t a0, uint32_t a1, uint32_t a2,
                                         uint32_t a3, uint32_t b0, uint32_t b1) {
    asm volatile("mma.sync.aligned.m16n8k16.row.col.f32.f16.f16.f32 "
                 "{%0,%1,%2,%3}, {%4,%5,%6,%7}, {%8,%9}, {%0,%1,%2,%3};"
                 : "+f"(c[0]), "+f"(c[1]), "+f"(c[2]), "+f"(c[3])
                 : "r"(a0), "r"(a1), "r"(a2), "r"(a3), "r"(b0), "r"(b1));
}
__device__ __forceinline__ void cp16(uint32_t dst, const void* src) {
    asm volatile("cp.async.cg.shared.global [%0], [%1], 16;" :: "r"(dst), "l"(src) : "memory");
}
#define CP_COMMIT() asm volatile("cp.async.commit_group;" ::: "memory")
#define CP_WAIT0()  asm volatile("cp.async.wait_group 0;" ::: "memory")

__device__ __forceinline__ uint32_t packh(__half a, __half b) {
    __half2 t(a, b);
    return *reinterpret_cast<uint32_t*>(&t);
}

// ================= device scratch =================
__device__ float g_top_v[2 * NTOK];
__device__ int   g_top_e[2 * NTOK];
__device__ float g_importance[NEXP];
__device__ int   g_counts[NEXP];
__device__ int   g_cursor[NEXP];
__device__ int   g_bucket_tok[2 * NTOK];
__device__ float g_bucket_w[2 * NTOK];
__device__ int   g_tok_slot[2 * NTOK];
__device__ __align__(16) __half g_partial_h[(size_t)2 * NTOK * DMODEL];

__device__ __align__(16) __half g_xh[NTOK * DMODEL];
__device__ __align__(16) __half g_w1h[NEXP * HDIM * DMODEL];   // [E,H,D] (transposed)
__device__ __align__(16) __half g_w2h[NEXP * DMODEL * HDIM];   // [E,D,H] (transposed)

// ================= kernel: coalesced transpose-convert weights (+ init in block 0) =================
// 2048 blocks: [0,1024) W1 tiles, [1024,2048) W2 tiles. 32x32 tile via padded smem.
__global__ void __launch_bounds__(256) convert_w_kernel(const float* __restrict__ W1,
                                                        const float* __restrict__ W2) {
    __shared__ float tile[32][33];
    const int b = blockIdx.x;
    const int tx = threadIdx.x & 31;
    const int ty = threadIdx.x >> 5;         // 0..7

    if (b == 0 && threadIdx.x < NEXP) {
        g_counts[threadIdx.x] = 0;
        g_cursor[threadIdx.x] = 0;
        g_importance[threadIdx.x] = 0.f;
    }

    if (b < 1024) {
        // W1 [E,128d,256h] -> W1T [E,256h,128d]
        int e = b >> 5, r = b & 31;
        int dblk = r >> 3, hblk = r & 7;
        const float* src = W1 + ((size_t)e * 128 + dblk * 32) * 256 + hblk * 32;
        #pragma unroll
        for (int i = 0; i < 4; ++i)
            tile[ty + i * 8][tx] = src[(size_t)(ty + i * 8) * 256 + tx];
        __syncthreads();
        __half* dst = g_w1h + ((size_t)e * 256 + hblk * 32) * 128 + dblk * 32;
        #pragma unroll
        for (int i = 0; i < 4; ++i)
            dst[(size_t)(ty + i * 8) * 128 + tx] = __float2half_rn(tile[tx][ty + i * 8]);
    } else {
        // W2 [E,256h,128d] -> W2T [E,128d,256h]
        int bb = b - 1024;
        int e = bb >> 5, r = bb & 31;
        int hblk = r >> 2, dblk = r & 3;
        const float* src = W2 + ((size_t)e * 256 + hblk * 32) * 128 + dblk * 32;
        #pragma unroll
        for (int i = 0; i < 4; ++i)
            tile[ty + i * 8][tx] = src[(size_t)(ty + i * 8) * 128 + tx];
        __syncthreads();
        __half* dst = g_w2h + ((size_t)e * 128 + dblk * 32) * 256 + hblk * 32;
        #pragma unroll
        for (int i = 0; i < 4; ++i)
            dst[(size_t)(ty + i * 8) * 256 + tx] = __float2half_rn(tile[tx][ty + i * 8]);
    }
}

// ================= kernel: router (thread per token; also emits x as fp16) =================
__global__ void __launch_bounds__(256) router_kernel(
    const float* __restrict__ x, const float* __restrict__ Wr,
    const float* __restrict__ br)
{
    __shared__ float wr_s[DMODEL * NEXP];
    __shared__ float br_s[NEXP];
    __shared__ float imp_s[NEXP];
    __shared__ int   cnt_s[NEXP];

    const int tid = threadIdx.x;
    if (tid < NEXP) { imp_s[tid] = 0.f; cnt_s[tid] = 0; br_s[tid] = br[tid]; }
    #pragma unroll
    for (int i = tid; i < DMODEL * NEXP; i += 256) wr_s[i] = Wr[i];
    __syncthreads();

    const int n = blockIdx.x * 256 + tid;

    float acc[NEXP];
    #pragma unroll
    for (int e = 0; e < NEXP; ++e) acc[e] = br_s[e];

    const float4* xrow = reinterpret_cast<const float4*>(x + (size_t)n * DMODEL);
    float4 xv = xrow[0];
    uint32_t hprev0 = 0, hprev1 = 0;
    #pragma unroll 4
    for (int ch = 0; ch < 32; ++ch) {
        float4 xn;
        if (ch < 31) xn = xrow[ch + 1];

        uint32_t p0 = packh(__float2half_rn(xv.x), __float2half_rn(xv.y));
        uint32_t p1 = packh(__float2half_rn(xv.z), __float2half_rn(xv.w));
        if (ch & 1) {
            *reinterpret_cast<uint4*>(g_xh + (size_t)n * DMODEL + (ch - 1) * 4) =
                make_uint4(hprev0, hprev1, p0, p1);
        } else { hprev0 = p0; hprev1 = p1; }

        float xd[4] = {xv.x, xv.y, xv.z, xv.w};
        #pragma unroll
        for (int dd = 0; dd < 4; ++dd) {
            const float4* wrow = reinterpret_cast<const float4*>(&wr_s[(ch * 4 + dd) * NEXP]);
            #pragma unroll
            for (int e4 = 0; e4 < 8; ++e4) {
                float4 w = wrow[e4];
                acc[e4 * 4 + 0] = fmaf(xd[dd], w.x, acc[e4 * 4 + 0]);
                acc[e4 * 4 + 1] = fmaf(xd[dd], w.y, acc[e4 * 4 + 1]);
                acc[e4 * 4 + 2] = fmaf(xd[dd], w.z, acc[e4 * 4 + 2]);
                acc[e4 * 4 + 3] = fmaf(xd[dd], w.w, acc[e4 * 4 + 3]);
            }
        }
        xv = xn;
    }

    float mx = acc[0];
    #pragma unroll
    for (int e = 1; e < NEXP; ++e) mx = fmaxf(mx, acc[e]);
    float s = 0.f;
    #pragma unroll
    for (int e = 0; e < NEXP; ++e) { acc[e] = expf(acc[e] - mx); s += acc[e]; }
    float inv = 1.f / s;
    #pragma unroll
    for (int e = 0; e < NEXP; ++e) acc[e] *= inv;

    float v1 = acc[0]; int i1 = 0;
    #pragma unroll
    for (int e = 1; e < NEXP; ++e) if (acc[e] > v1) { v1 = acc[e]; i1 = e; }
    float v2 = -1.f; int i2 = 0;
    #pragma unroll
    for (int e = 0; e < NEXP; ++e) {
        bool ok = (e != i1) && (acc[e] > v2);
        if (ok) { v2 = acc[e]; i2 = e; }
    }

    g_top_e[2 * n]     = i1;  g_top_v[2 * n]     = v1;
    g_top_e[2 * n + 1] = i2;  g_top_v[2 * n + 1] = v2;
    atomicAdd(&imp_s[i1], v1);
    atomicAdd(&imp_s[i2], v2);
    atomicAdd(&cnt_s[i1], 1);
    atomicAdd(&cnt_s[i2], 1);

    __syncthreads();
    if (tid < NEXP) {
        atomicAdd(&g_importance[tid], imp_s[tid]);
        atomicAdd(&g_counts[tid], cnt_s[tid]);
    }
}

// ================= kernel: scatter (computes offsets locally; block 0 writes loss) =================
__global__ void __launch_bounds__(256) scatter_kernel(float* __restrict__ out, int out_size) {
    __shared__ int offs[NEXP];
    __shared__ int lcnt[NEXP];
    __shared__ int gbase[NEXP];
    __shared__ int lcur[NEXP];

    const int tid = threadIdx.x;
    const unsigned FULL = 0xffffffffu;

    if (tid < 32) {
        int c = g_counts[tid];
        int sc = c;
        #pragma unroll
        for (int o = 1; o < 32; o <<= 1) {
            int v = __shfl_up_sync(FULL, sc, o);
            if (tid >= o) sc += v;
        }
        offs[tid] = sc - c;
        lcnt[tid] = 0;
    }
    // block 0, warp 1: load-balancing loss
    if (blockIdx.x == 0 && (tid >> 5) == 1) {
        int lane = tid & 31;
        float imp = g_importance[lane];
        float s = imp;
        #pragma unroll
        for (int o = 16; o; o >>= 1) s += __shfl_xor_sync(FULL, s, o);
        float mean = s / 32.f;
        float d = imp - mean;
        float ss = d * d;
        #pragma unroll
        for (int o = 16; o; o >>= 1) ss += __shfl_xor_sync(FULL, ss, o);
        float var = ss / 31.f;
        if (lane == 0 && out_size > NTOK * DMODEL)
            out[NTOK * DMODEL] = var / (mean * mean + 1e-9f);
    }
    __syncthreads();

    const int n = blockIdx.x * 256 + tid;
    int e0 = g_top_e[2 * n];     float v0 = g_top_v[2 * n];
    int e1 = g_top_e[2 * n + 1]; float v1 = g_top_v[2 * n + 1];
    atomicAdd(&lcnt[e0], 1);
    atomicAdd(&lcnt[e1], 1);
    __syncthreads();

    if (tid < NEXP) { gbase[tid] = offs[tid] + atomicAdd(&g_cursor[tid], lcnt[tid]); lcur[tid] = 0; }
    __syncthreads();

    int p0 = gbase[e0] + atomicAdd(&lcur[e0], 1);
    g_bucket_tok[p0] = n; g_bucket_w[p0] = v0; g_tok_slot[2 * n] = p0;
    int p1 = gbase[e1] + atomicAdd(&lcur[e1], 1);
    g_bucket_tok[p1] = n; g_bucket_w[p1] = v1; g_tok_slot[2 * n + 1] = p1;
}

// ================= kernel: grouped expert GEMM (pure fp16, TM=64, 4 CTA/SM) =================
#define RW128 272
#define RW64  144
#define O_XH  0
#define O_BH  17408
#define O_CH  35840
#define O_TOK 45056
#define O_WSM (O_TOK + 256)
#define O_B1  (O_TOK + 512)
#define O_B2  (O_TOK + 1536)
#define O_CNT (O_TOK + 2048)
#define O_OFF (O_TOK + 2176)
#define O_TF  (O_TOK + 2304)      // 33 ints
#define SMEM_DYN (O_TOK + 2560)   // 47616

#define NTHR 256

__global__ void __launch_bounds__(NTHR, 4) expert_mma_kernel(
    const float* __restrict__ b1, const float* __restrict__ b2)
{
    const int t = blockIdx.x;

    extern __shared__ char smp[];
    const uint32_t sbase = smem_to_u32(smp);
    int*   toks_s = (int*)(smp + O_TOK);
    float* wsm_s  = (float*)(smp + O_WSM);
    float* b1s    = (float*)(smp + O_B1);
    float* b2s    = (float*)(smp + O_B2);
    int*   cnt_s  = (int*)(smp + O_CNT);
    int*   off_s  = (int*)(smp + O_OFF);
    int*   tf_s   = (int*)(smp + O_TF);

    const int tid = threadIdx.x;
    const int wid = tid >> 5;
    const int lane = tid & 31;
    const unsigned FULL = 0xffffffffu;

    // local tile map from g_counts (replaces scan kernel)
    if (wid == 0) {
        int c = g_counts[lane];
        int sc = c;
        #pragma unroll
        for (int o = 1; o < 32; o <<= 1) {
            int v = __shfl_up_sync(FULL, sc, o);
            if (lane >= o) sc += v;
        }
        off_s[lane] = sc - c;
        cnt_s[lane] = c;
        int nt = (c + TM - 1) / TM;
        int st = nt;
        #pragma unroll
        for (int o = 1; o < 32; o <<= 1) {
            int v = __shfl_up_sync(FULL, st, o);
            if (lane >= o) st += v;
        }
        tf_s[lane + 1] = st;
        if (lane == 0) tf_s[0] = 0;
    }
    __syncthreads();
    if (t >= tf_s[NEXP]) return;

    int e = 0;
    #pragma unroll 1
    while (t >= tf_s[e + 1]) ++e;
    const int mtile = t - tf_s[e];
    const int off   = off_s[e];
    const int cnt   = cnt_s[e];
    const int m0g   = mtile * TM;
    const int valid = min(TM, cnt - m0g);

    if (tid < 64) {
        if (tid < valid) {
            toks_s[tid] = g_bucket_tok[off + m0g + tid];
            wsm_s[tid]  = g_bucket_w[off + m0g + tid];
        } else { toks_s[tid] = 0; wsm_s[tid] = 0.f; }
    }
    if (tid < 128) b2s[tid] = b2[e * DMODEL + tid];
    b1s[tid] = b1[e * HDIM + tid];
    __syncthreads();

    // ---- async gather X rows [64,128] fp16 ----
    #pragma unroll
    for (int i = tid; i < 1024; i += NTHR) {
        int r = i >> 4, ch = i & 15;
        const size_t src = (size_t)toks_s[r] * DMODEL + ch * 8;
        cp16(sbase + O_XH + r * RW128 + ch * 16, g_xh + src);
    }

    const size_t w1base = (size_t)e * HDIM * DMODEL;
    const size_t w2base = (size_t)e * DMODEL * HDIM;

    // ---- async load W1 chunk 0: [64h, 128d] fp16 ----
    #pragma unroll
    for (int i = tid; i < 1024; i += NTHR) {
        int r = i >> 4, ch = i & 15;
        size_t src = w1base + (size_t)r * DMODEL + ch * 8;
        cp16(sbase + O_BH + r * RW128 + ch * 16, g_w1h + src);
    }
    CP_COMMIT();
    CP_WAIT0();
    __syncthreads();

    // warp tiling: 4 m-warps (16 rows) x 2 n-warps
    const int m0 = (wid >> 1) * 16;
    const int nw = wid & 1;
    const uint32_t arow  = m0 + (lane & 15);
    const uint32_t acolb = ((lane >> 4) & 1) * 16;
    const uint32_t brsub = ((lane >> 4) & 1) * 8 + (lane & 7);
    const uint32_t bcolb = ((lane >> 3) & 1) * 16;

    float acc2[8][4];
    #pragma unroll
    for (int j = 0; j < 8; ++j)
        #pragma unroll
        for (int q = 0; q < 4; ++q) acc2[j][q] = 0.f;

    #pragma unroll 1
    for (int c = 0; c < 4; ++c) {
        // ---- FC1: h_c[64,64] = X[64,128] @ W1c[64,128]^T ; warp m16 x n32 ----
        float acc1[4][4];
        #pragma unroll
        for (int j = 0; j < 4; ++j)
            #pragma unroll
            for (int q = 0; q < 4; ++q) acc1[j][q] = 0.f;

        #pragma unroll 1
        for (int k = 0; k < 8; ++k) {
            uint32_t aaddr = sbase + O_XH + arow * RW128 + k * 32 + acolb;
            uint32_t ah0, ah1, ah2, ah3;
            ldsm4(ah0, ah1, ah2, ah3, aaddr);
            #pragma unroll
            for (int jp = 0; jp < 2; ++jp) {
                uint32_t brow = nw * 32 + jp * 16 + brsub;
                uint32_t baddr = sbase + O_BH + brow * RW128 + k * 32 + bcolb;
                uint32_t bh0, bh1, bh2, bh3;
                ldsm4(bh0, bh1, bh2, bh3, baddr);
                mma16816(acc1[2 * jp],     ah0, ah1, ah2, ah3, bh0, bh1);
                mma16816(acc1[2 * jp + 1], ah0, ah1, ah2, ah3, bh2, bh3);
            }
        }
        __syncthreads();   // W1c consumed

        // ---- prefetch W2 chunk c: [128d, 64h] (overlaps epilogue) ----
        #pragma unroll
        for (int i = tid; i < 1024; i += NTHR) {
            int r = i >> 3, ch = i & 7;
            size_t src = w2base + (size_t)r * HDIM + c * 64 + ch * 8;
            cp16(sbase + O_BH + r * RW64 + ch * 16, g_w2h + src);
        }
        CP_COMMIT();

        // ---- epilogue 1: relu(acc1 + b1) -> fp16 into C [64,64] ----
        {
            const int r0 = m0 + (lane >> 2);
            const int cb = (lane & 3) * 2;
            #pragma unroll
            for (int jn = 0; jn < 4; ++jn) {
                const float* a = acc1[jn];
                int coll = nw * 32 + jn * 8 + cb;
                int colg = c * 64 + coll;
                float bb0 = b1s[colg], bb1 = b1s[colg + 1];
                __half h0 = __float2half_rn(fmaxf(a[0] + bb0, 0.f));
                __half h1 = __float2half_rn(fmaxf(a[1] + bb1, 0.f));
                __half h2 = __float2half_rn(fmaxf(a[2] + bb0, 0.f));
                __half h3 = __float2half_rn(fmaxf(a[3] + bb1, 0.f));
                *reinterpret_cast<uint32_t*>(smp + O_CH + r0 * RW64 + coll * 2) = packh(h0, h1);
                *reinterpret_cast<uint32_t*>(smp + O_CH + (r0 + 8) * RW64 + coll * 2) = packh(h2, h3);
            }
        }
        CP_WAIT0();
        __syncthreads();   // W2c ready, h visible

        // ---- FC2: acc2 += h_c[64,64] @ W2c[128,64]^T ; warp m16 x n64 ----
        #pragma unroll 1
        for (int k = 0; k < 4; ++k) {
            uint32_t aaddr = sbase + O_CH + arow * RW64 + k * 32 + acolb;
            uint32_t ah0, ah1, ah2, ah3;
            ldsm4(ah0, ah1, ah2, ah3, aaddr);
            #pragma unroll
            for (int jp = 0; jp < 4; ++jp) {
                uint32_t brow = nw * 64 + jp * 16 + brsub;
                uint32_t baddr = sbase + O_BH + brow * RW64 + k * 32 + bcolb;
                uint32_t bh0, bh1, bh2, bh3;
                ldsm4(bh0, bh1, bh2, bh3, baddr);
                mma16816(acc2[2 * jp],     ah0, ah1, ah2, ah3, bh0, bh1);
                mma16816(acc2[2 * jp + 1], ah0, ah1, ah2, ah3, bh2, bh3);
            }
        }
        __syncthreads();   // W2c + C consumed

        // ---- prefetch W1 chunk c+1 ----
        if (c < 3) {
            #pragma unroll
            for (int i = tid; i < 1024; i += NTHR) {
                int r = i >> 4, ch = i & 15;
                size_t src = w1base + (size_t)((c + 1) * 64 + r) * DMODEL + ch * 8;
                cp16(sbase + O_BH + r * RW128 + ch * 16, g_w1h + src);
            }
            CP_COMMIT();
            CP_WAIT0();
            __syncthreads();
        }
    }

    // ---- epilogue 2: w * (acc2 + b2) -> g_partial_h (fp16) ----
    {
        const int cb = (lane & 3) * 2;
        const int r0 = m0 + (lane >> 2);
        const int r1 = r0 + 8;
        const float w0 = (r0 < valid) ? wsm_s[r0] : 0.f;
        const float w1 = (r1 < valid) ? wsm_s[r1] : 0.f;
        const size_t s0 = (size_t)(off + m0g + r0) * DMODEL;
        const size_t s1 = (size_t)(off + m0g + r1) * DMODEL;
        #pragma unroll
        for (int jn = 0; jn < 8; ++jn) {
            const float* a = acc2[jn];
            int col = nw * 64 + jn * 8 + cb;
            float bb0 = b2s[col], bb1 = b2s[col + 1];
            if (r0 < valid) {
                __half q0 = __float2half_rn(w0 * (a[0] + bb0));
                __half q1 = __float2half_rn(w0 * (a[1] + bb1));
                *reinterpret_cast<uint32_t*>(&g_partial_h[s0 + col]) = packh(q0, q1);
            }
            if (r1 < valid) {
                __half q2 = __float2half_rn(w1 * (a[2] + bb0));
                __half q3 = __float2half_rn(w1 * (a[3] + bb1));
                *reinterpret_cast<uint32_t*>(&g_partial_h[s1 + col]) = packh(q2, q3);
            }
        }
    }
}

// ================= kernel: combine (fp16 partials -> fp32 out) =================
__global__ void __launch_bounds__(256) combine_kernel(float* __restrict__ out) {
    int gid = blockIdx.x * 256 + threadIdx.x;
    int n = gid >> 4;
    int q = gid & 15;
    int s0 = g_tok_slot[2 * n];
    int s1 = g_tok_slot[2 * n + 1];
    const uint4* P = reinterpret_cast<const uint4*>(g_partial_h);
    uint4 u0 = P[(size_t)s0 * 16 + q];
    uint4 u1 = P[(size_t)s1 * 16 + q];
    const __half2* h0 = reinterpret_cast<const __half2*>(&u0);
    const __half2* h1 = reinterpret_cast<const __half2*>(&u1);
    float4 o0, o1;
    float2 a0 = __half22float2(h0[0]), b0 = __half22float2(h1[0]);
    float2 a1 = __half22float2(h0[1]), b1 = __half22float2(h1[1]);
    float2 a2 = __half22float2(h0[2]), b2 = __half22float2(h1[2]);
    float2 a3 = __half22float2(h0[3]), b3 = __half22float2(h1[3]);
    o0.x = a0.x + b0.x; o0.y = a0.y + b0.y;
    o0.z = a1.x + b1.x; o0.w = a1.y + b1.y;
    o1.x = a2.x + b2.x; o1.y = a2.y + b2.y;
    o1.z = a3.x + b3.x; o1.w = a3.y + b3.y;
    float4* O = reinterpret_cast<float4*>(out);
    O[(size_t)n * 32 + q * 2]     = o0;
    O[(size_t)n * 32 + q * 2 + 1] = o1;
}

// ================= launch =================
extern "C" void kernel_launch(void* const* d_in, const int* in_sizes, int n_in,
                              void* d_out, int out_size) {
    const float* x  = (const float*)d_in[0];
    const float* W1 = (const float*)d_in[1];
    const float* b1 = (const float*)d_in[2];
    const float* W2 = (const float*)d_in[3];
    const float* b2 = (const float*)d_in[4];
    const float* Wr = (const float*)d_in[5];
    const float* br = (const float*)d_in[6];
    float* out = (float*)d_out;

    cudaFuncSetAttribute(expert_mma_kernel,
                         cudaFuncAttributeMaxDynamicSharedMemorySize, SMEM_DYN);

    convert_w_kernel<<<2048, 256>>>(W1, W2);
    router_kernel<<<NTOK / 256, 256>>>(x, Wr, br);
    scatter_kernel<<<NTOK / 256, 256>>>(out, out_size);
    expert_mma_kernel<<<2080, NTHR, SMEM_DYN>>>(b1, b2);
    combine_kernel<<<(NTOK * 16) / 256, 256>>>(out);
}

// round 13
// speedup vs baseline: 1.1635x; 1.1010x over previous
#include <cuda_runtime.h>
#include <cuda_fp16.h>
#include <math.h>
#include <stdint.h>

#define NTOK   65536
#define DMODEL 128
#define HDIM   256
#define NEXP   32
#define TM     128

// ================= helpers =================
__device__ __forceinline__ uint32_t smem_to_u32(const void* p) {
    uint32_t a;
    asm("{ .reg .u64 t; cvta.to.shared.u64 t, %1; cvt.u32.u64 %0, t; }" : "=r"(a) : "l"(p));
    return a;
}
__device__ __forceinline__ void ldsm4(uint32_t& r0, uint32_t& r1, uint32_t& r2, uint32_t& r3,
                                      uint32_t addr) {
    asm volatile("ldmatrix.sync.aligned.m8n8.x4.shared.b16 {%0,%1,%2,%3}, [%4];"
                 : "=r"(r0), "=r"(r1), "=r"(r2), "=r"(r3) : "r"(addr));
}
__device__ __forceinline__ void mma16816(float* c, uint32_t a0, uint32_t a1, uint32_t a2,
                                         uint32_t a3, uint32_t b0, uint32_t b1) {
    asm volatile("mma.sync.aligned.m16n8k16.row.col.f32.f16.f16.f32 "
                 "{%0,%1,%2,%3}, {%4,%5,%6,%7}, {%8,%9}, {%0,%1,%2,%3};"
                 : "+f"(c[0]), "+f"(c[1]), "+f"(c[2]), "+f"(c[3])
                 : "r"(a0), "r"(a1), "r"(a2), "r"(a3), "r"(b0), "r"(b1));
}
__device__ __forceinline__ void cp16(uint32_t dst, const void* src) {
    asm volatile("cp.async.cg.shared.global [%0], [%1], 16;" :: "r"(dst), "l"(src) : "memory");
}
#define CP_COMMIT() asm volatile("cp.async.commit_group;" ::: "memory")
#define CP_WAIT0()  asm volatile("cp.async.wait_group 0;" ::: "memory")

__device__ __forceinline__ uint32_t packh(__half a, __half b) {
    __half2 t(a, b);
    return *reinterpret_cast<uint32_t*>(&t);
}

// ================= device scratch =================
__device__ float g_top_v[2 * NTOK];
__device__ int   g_top_e[2 * NTOK];
__device__ float g_importance[NEXP];
__device__ int   g_counts[NEXP];
__device__ int   g_cursor[NEXP];
__device__ int   g_bucket_tok[2 * NTOK];
__device__ float g_bucket_w[2 * NTOK];
__device__ int   g_tok_slot[2 * NTOK];
__device__ __align__(16) __half g_partial_h[(size_t)2 * NTOK * DMODEL];

__device__ __align__(16) __half g_xh[NTOK * DMODEL];
__device__ __align__(16) __half g_w1h[NEXP * HDIM * DMODEL];   // [E,H,D]
__device__ __align__(16) __half g_w2h[NEXP * DMODEL * HDIM];   // [E,D,H]

// ================= kernel: coalesced transpose-convert weights (+ init in block 0) =================
__global__ void __launch_bounds__(256) convert_w_kernel(const float* __restrict__ W1,
                                                        const float* __restrict__ W2) {
    __shared__ float tile[32][33];
    const int b = blockIdx.x;
    const int tx = threadIdx.x & 31;
    const int ty = threadIdx.x >> 5;

    if (b == 0 && threadIdx.x < NEXP) {
        g_counts[threadIdx.x] = 0;
        g_cursor[threadIdx.x] = 0;
        g_importance[threadIdx.x] = 0.f;
    }

    if (b < 1024) {
        int e = b >> 5, r = b & 31;
        int dblk = r >> 3, hblk = r & 7;
        const float* src = W1 + ((size_t)e * 128 + dblk * 32) * 256 + hblk * 32;
        #pragma unroll
        for (int i = 0; i < 4; ++i)
            tile[ty + i * 8][tx] = src[(size_t)(ty + i * 8) * 256 + tx];
        __syncthreads();
        __half* dst = g_w1h + ((size_t)e * 256 + hblk * 32) * 128 + dblk * 32;
        #pragma unroll
        for (int i = 0; i < 4; ++i)
            dst[(size_t)(ty + i * 8) * 128 + tx] = __float2half_rn(tile[tx][ty + i * 8]);
    } else {
        int bb = b - 1024;
        int e = bb >> 5, r = bb & 31;
        int hblk = r >> 2, dblk = r & 3;
        const float* src = W2 + ((size_t)e * 256 + hblk * 32) * 128 + dblk * 32;
        #pragma unroll
        for (int i = 0; i < 4; ++i)
            tile[ty + i * 8][tx] = src[(size_t)(ty + i * 8) * 128 + tx];
        __syncthreads();
        __half* dst = g_w2h + ((size_t)e * 128 + dblk * 32) * 256 + hblk * 32;
        #pragma unroll
        for (int i = 0; i < 4; ++i)
            dst[(size_t)(ty + i * 8) * 256 + tx] = __float2half_rn(tile[tx][ty + i * 8]);
    }
}

// ================= kernel: router (thread per token; also emits x as fp16) =================
__global__ void __launch_bounds__(256) router_kernel(
    const float* __restrict__ x, const float* __restrict__ Wr,
    const float* __restrict__ br)
{
    __shared__ float wr_s[DMODEL * NEXP];
    __shared__ float br_s[NEXP];
    __shared__ float imp_s[NEXP];
    __shared__ int   cnt_s[NEXP];

    const int tid = threadIdx.x;
    if (tid < NEXP) { imp_s[tid] = 0.f; cnt_s[tid] = 0; br_s[tid] = br[tid]; }
    #pragma unroll
    for (int i = tid; i < DMODEL * NEXP; i += 256) wr_s[i] = Wr[i];
    __syncthreads();

    const int n = blockIdx.x * 256 + tid;

    float acc[NEXP];
    #pragma unroll
    for (int e = 0; e < NEXP; ++e) acc[e] = br_s[e];

    const float4* xrow = reinterpret_cast<const float4*>(x + (size_t)n * DMODEL);
    float4 xv = xrow[0];
    uint32_t hprev0 = 0, hprev1 = 0;
    #pragma unroll 4
    for (int ch = 0; ch < 32; ++ch) {
        float4 xn;
        if (ch < 31) xn = xrow[ch + 1];

        uint32_t p0 = packh(__float2half_rn(xv.x), __float2half_rn(xv.y));
        uint32_t p1 = packh(__float2half_rn(xv.z), __float2half_rn(xv.w));
        if (ch & 1) {
            *reinterpret_cast<uint4*>(g_xh + (size_t)n * DMODEL + (ch - 1) * 4) =
                make_uint4(hprev0, hprev1, p0, p1);
        } else { hprev0 = p0; hprev1 = p1; }

        float xd[4] = {xv.x, xv.y, xv.z, xv.w};
        #pragma unroll
        for (int dd = 0; dd < 4; ++dd) {
            const float4* wrow = reinterpret_cast<const float4*>(&wr_s[(ch * 4 + dd) * NEXP]);
            #pragma unroll
            for (int e4 = 0; e4 < 8; ++e4) {
                float4 w = wrow[e4];
                acc[e4 * 4 + 0] = fmaf(xd[dd], w.x, acc[e4 * 4 + 0]);
                acc[e4 * 4 + 1] = fmaf(xd[dd], w.y, acc[e4 * 4 + 1]);
                acc[e4 * 4 + 2] = fmaf(xd[dd], w.z, acc[e4 * 4 + 2]);
                acc[e4 * 4 + 3] = fmaf(xd[dd], w.w, acc[e4 * 4 + 3]);
            }
        }
        xv = xn;
    }

    float mx = acc[0];
    #pragma unroll
    for (int e = 1; e < NEXP; ++e) mx = fmaxf(mx, acc[e]);
    float s = 0.f;
    #pragma unroll
    for (int e = 0; e < NEXP; ++e) { acc[e] = expf(acc[e] - mx); s += acc[e]; }
    float inv = 1.f / s;
    #pragma unroll
    for (int e = 0; e < NEXP; ++e) acc[e] *= inv;

    float v1 = acc[0]; int i1 = 0;
    #pragma unroll
    for (int e = 1; e < NEXP; ++e) if (acc[e] > v1) { v1 = acc[e]; i1 = e; }
    float v2 = -1.f; int i2 = 0;
    #pragma unroll
    for (int e = 0; e < NEXP; ++e) {
        bool ok = (e != i1) && (acc[e] > v2);
        if (ok) { v2 = acc[e]; i2 = e; }
    }

    g_top_e[2 * n]     = i1;  g_top_v[2 * n]     = v1;
    g_top_e[2 * n + 1] = i2;  g_top_v[2 * n + 1] = v2;
    atomicAdd(&imp_s[i1], v1);
    atomicAdd(&imp_s[i2], v2);
    atomicAdd(&cnt_s[i1], 1);
    atomicAdd(&cnt_s[i2], 1);

    __syncthreads();
    if (tid < NEXP) {
        atomicAdd(&g_importance[tid], imp_s[tid]);
        atomicAdd(&g_counts[tid], cnt_s[tid]);
    }
}

// ================= kernel: scatter (computes offsets locally; block 0 writes loss) =================
__global__ void __launch_bounds__(256) scatter_kernel(float* __restrict__ out, int out_size) {
    __shared__ int offs[NEXP];
    __shared__ int lcnt[NEXP];
    __shared__ int gbase[NEXP];
    __shared__ int lcur[NEXP];

    const int tid = threadIdx.x;
    const unsigned FULL = 0xffffffffu;

    if (tid < 32) {
        int c = g_counts[tid];
        int sc = c;
        #pragma unroll
        for (int o = 1; o < 32; o <<= 1) {
            int v = __shfl_up_sync(FULL, sc, o);
            if (tid >= o) sc += v;
        }
        offs[tid] = sc - c;
        lcnt[tid] = 0;
    }
    if (blockIdx.x == 0 && (tid >> 5) == 1) {
        int lane = tid & 31;
        float imp = g_importance[lane];
        float s = imp;
        #pragma unroll
        for (int o = 16; o; o >>= 1) s += __shfl_xor_sync(FULL, s, o);
        float mean = s / 32.f;
        float d = imp - mean;
        float ss = d * d;
        #pragma unroll
        for (int o = 16; o; o >>= 1) ss += __shfl_xor_sync(FULL, ss, o);
        float var = ss / 31.f;
        if (lane == 0 && out_size > NTOK * DMODEL)
            out[NTOK * DMODEL] = var / (mean * mean + 1e-9f);
    }
    __syncthreads();

    const int n = blockIdx.x * 256 + tid;
    int e0 = g_top_e[2 * n];     float v0 = g_top_v[2 * n];
    int e1 = g_top_e[2 * n + 1]; float v1 = g_top_v[2 * n + 1];
    atomicAdd(&lcnt[e0], 1);
    atomicAdd(&lcnt[e1], 1);
    __syncthreads();

    if (tid < NEXP) { gbase[tid] = offs[tid] + atomicAdd(&g_cursor[tid], lcnt[tid]); lcur[tid] = 0; }
    __syncthreads();

    int p0 = gbase[e0] + atomicAdd(&lcur[e0], 1);
    g_bucket_tok[p0] = n; g_bucket_w[p0] = v0; g_tok_slot[2 * n] = p0;
    int p1 = gbase[e1] + atomicAdd(&lcur[e1], 1);
    g_bucket_tok[p1] = n; g_bucket_w[p1] = v1; g_tok_slot[2 * n + 1] = p1;
}

// ================= kernel: grouped expert GEMM (fp16, TM=128, m32 warps, 2 CTA/SM) =================
// X @ O_XH : [128,128] fp16, stride 272   (34816 B)
// W @ O_BH : W1c [64h,128d] s272 (17408) OR W2c [128d,64h] s144 (18432)
// C @ O_CH : h chunk [128,64] s144        (18432 B)
#define RW128 272
#define RW64  144
#define O_XH  0
#define O_BH  34816
#define O_CH  53248
#define O_TOK 71680
#define O_WSM (O_TOK + 512)
#define O_B1  (O_TOK + 1024)
#define O_B2  (O_TOK + 2048)
#define O_CNT (O_TOK + 2560)
#define O_OFF (O_TOK + 2688)
#define O_TF  (O_TOK + 2816)
#define SMEM_DYN (O_TOK + 3072)   // 74752

#define NTHR 256

__global__ void __launch_bounds__(NTHR, 2) expert_mma_kernel(
    const float* __restrict__ b1, const float* __restrict__ b2)
{
    const int t = blockIdx.x;

    extern __shared__ char smp[];
    const uint32_t sbase = smem_to_u32(smp);
    int*   toks_s = (int*)(smp + O_TOK);
    float* wsm_s  = (float*)(smp + O_WSM);
    float* b1s    = (float*)(smp + O_B1);
    float* b2s    = (float*)(smp + O_B2);
    int*   cnt_s  = (int*)(smp + O_CNT);
    int*   off_s  = (int*)(smp + O_OFF);
    int*   tf_s   = (int*)(smp + O_TF);

    const int tid = threadIdx.x;
    const int wid = tid >> 5;
    const int lane = tid & 31;
    const unsigned FULL = 0xffffffffu;

    // tile map from g_counts (TM=128)
    if (wid == 0) {
        int c = g_counts[lane];
        int sc = c;
        #pragma unroll
        for (int o = 1; o < 32; o <<= 1) {
            int v = __shfl_up_sync(FULL, sc, o);
            if (lane >= o) sc += v;
        }
        off_s[lane] = sc - c;
        cnt_s[lane] = c;
        int nt = (c + TM - 1) / TM;
        int st = nt;
        #pragma unroll
        for (int o = 1; o < 32; o <<= 1) {
            int v = __shfl_up_sync(FULL, st, o);
            if (lane >= o) st += v;
        }
        tf_s[lane + 1] = st;
        if (lane == 0) tf_s[0] = 0;
    }
    __syncthreads();
    if (t >= tf_s[NEXP]) return;

    int e = 0;
    #pragma unroll 1
    while (t >= tf_s[e + 1]) ++e;
    const int mtile = t - tf_s[e];
    const int off   = off_s[e];
    const int cnt   = cnt_s[e];
    const int m0g   = mtile * TM;
    const int valid = min(TM, cnt - m0g);

    if (tid < 128) {
        if (tid < valid) {
            toks_s[tid] = g_bucket_tok[off + m0g + tid];
            wsm_s[tid]  = g_bucket_w[off + m0g + tid];
        } else { toks_s[tid] = 0; wsm_s[tid] = 0.f; }
        b2s[tid] = b2[e * DMODEL + tid];
    }
    b1s[tid] = b1[e * HDIM + tid];
    __syncthreads();

    // ---- async gather X rows [128,128] fp16 ----
    #pragma unroll
    for (int i = tid; i < 2048; i += NTHR) {
        int r = i >> 4, ch = i & 15;
        const size_t src = (size_t)toks_s[r] * DMODEL + ch * 8;
        cp16(sbase + O_XH + r * RW128 + ch * 16, g_xh + src);
    }

    const size_t w1base = (size_t)e * HDIM * DMODEL;
    const size_t w2base = (size_t)e * DMODEL * HDIM;

    // ---- async load W1 chunk 0: [64h, 128d] ----
    #pragma unroll
    for (int i = tid; i < 1024; i += NTHR) {
        int r = i >> 4, ch = i & 15;
        size_t src = w1base + (size_t)r * DMODEL + ch * 8;
        cp16(sbase + O_BH + r * RW128 + ch * 16, g_w1h + src);
    }
    CP_COMMIT();
    CP_WAIT0();
    __syncthreads();

    // warp tiling: 4 m-warps (32 rows each) x 2 n-warps
    const int m0 = (wid >> 1) * 32;
    const int nw = wid & 1;
    const uint32_t arow  = m0 + (lane & 15);
    const uint32_t acolb = ((lane >> 4) & 1) * 16;
    const uint32_t brsub = ((lane >> 4) & 1) * 8 + (lane & 7);
    const uint32_t bcolb = ((lane >> 3) & 1) * 16;

    // acc2: [ms*8 + jn][4], ms<2 (rows m0+16*ms), jn<8 (d-cols nw*64 + jn*8)
    float acc2[16][4];
    #pragma unroll
    for (int j = 0; j < 16; ++j)
        #pragma unroll
        for (int q = 0; q < 4; ++q) acc2[j][q] = 0.f;

    #pragma unroll 1
    for (int c = 0; c < 4; ++c) {
        // ---- FC1: h_c[128,64] = X[128,128] @ W1c[64,128]^T ; warp m32 x n32 ----
        float acc1[8][4];   // [ms*4 + jn], jn<4 (h-cols nw*32 + jn*8)
        #pragma unroll
        for (int j = 0; j < 8; ++j)
            #pragma unroll
            for (int q = 0; q < 4; ++q) acc1[j][q] = 0.f;

        #pragma unroll 1
        for (int k = 0; k < 8; ++k) {
            uint32_t aaddr0 = sbase + O_XH + arow * RW128 + k * 32 + acolb;
            uint32_t ah[8];
            ldsm4(ah[0], ah[1], ah[2], ah[3], aaddr0);
            ldsm4(ah[4], ah[5], ah[6], ah[7], aaddr0 + 16 * RW128);
            #pragma unroll
            for (int jp = 0; jp < 2; ++jp) {
                uint32_t brow = nw * 32 + jp * 16 + brsub;
                uint32_t baddr = sbase + O_BH + brow * RW128 + k * 32 + bcolb;
                uint32_t bh0, bh1, bh2, bh3;
                ldsm4(bh0, bh1, bh2, bh3, baddr);
                #pragma unroll
                for (int ms = 0; ms < 2; ++ms) {
                    const uint32_t* A = ah + ms * 4;
                    mma16816(acc1[ms * 4 + 2 * jp],     A[0], A[1], A[2], A[3], bh0, bh1);
                    mma16816(acc1[ms * 4 + 2 * jp + 1], A[0], A[1], A[2], A[3], bh2, bh3);
                }
            }
        }
        __syncthreads();   // W1c consumed

        // ---- prefetch W2 chunk c: [128d, 64h] (overlaps epilogue) ----
        #pragma unroll
        for (int i = tid; i < 1024; i += NTHR) {
            int r = i >> 3, ch = i & 7;
            size_t src = w2base + (size_t)r * HDIM + c * 64 + ch * 8;
            cp16(sbase + O_BH + r * RW64 + ch * 16, g_w2h + src);
        }
        CP_COMMIT();

        // ---- epilogue 1: relu(acc1 + b1) -> fp16 into C [128,64] ----
        {
            const int cb = (lane & 3) * 2;
            #pragma unroll
            for (int ms = 0; ms < 2; ++ms) {
                const int r0 = m0 + ms * 16 + (lane >> 2);
                #pragma unroll
                for (int jn = 0; jn < 4; ++jn) {
                    const float* a = acc1[ms * 4 + jn];
                    int coll = nw * 32 + jn * 8 + cb;
                    int colg = c * 64 + coll;
                    float bb0 = b1s[colg], bb1 = b1s[colg + 1];
                    __half h0 = __float2half_rn(fmaxf(a[0] + bb0, 0.f));
                    __half h1 = __float2half_rn(fmaxf(a[1] + bb1, 0.f));
                    __half h2 = __float2half_rn(fmaxf(a[2] + bb0, 0.f));
                    __half h3 = __float2half_rn(fmaxf(a[3] + bb1, 0.f));
                    *reinterpret_cast<uint32_t*>(smp + O_CH + r0 * RW64 + coll * 2) = packh(h0, h1);
                    *reinterpret_cast<uint32_t*>(smp + O_CH + (r0 + 8) * RW64 + coll * 2) = packh(h2, h3);
                }
            }
        }
        CP_WAIT0();
        __syncthreads();   // W2c ready, h visible

        // ---- FC2: acc2 += h_c[128,64] @ W2c[128,64]^T ; warp m32 x n64 ----
        #pragma unroll 1
        for (int k = 0; k < 4; ++k) {
            uint32_t aaddr0 = sbase + O_CH + arow * RW64 + k * 32 + acolb;
            uint32_t ah[8];
            ldsm4(ah[0], ah[1], ah[2], ah[3], aaddr0);
            ldsm4(ah[4], ah[5], ah[6], ah[7], aaddr0 + 16 * RW64);
            #pragma unroll
            for (int jp = 0; jp < 4; ++jp) {
                uint32_t brow = nw * 64 + jp * 16 + brsub;
                uint32_t baddr = sbase + O_BH + brow * RW64 + k * 32 + bcolb;
                uint32_t bh0, bh1, bh2, bh3;
                ldsm4(bh0, bh1, bh2, bh3, baddr);
                #pragma unroll
                for (int ms = 0; ms < 2; ++ms) {
                    const uint32_t* A = ah + ms * 4;
                    mma16816(acc2[ms * 8 + 2 * jp],     A[0], A[1], A[2], A[3], bh0, bh1);
                    mma16816(acc2[ms * 8 + 2 * jp + 1], A[0], A[1], A[2], A[3], bh2, bh3);
                }
            }
        }
        __syncthreads();   // W2c + C consumed

        // ---- prefetch W1 chunk c+1 ----
        if (c < 3) {
            #pragma unroll
            for (int i = tid; i < 1024; i += NTHR) {
                int r = i >> 4, ch = i & 15;
                size_t src = w1base + (size_t)((c + 1) * 64 + r) * DMODEL + ch * 8;
                cp16(sbase + O_BH + r * RW128 + ch * 16, g_w1h + src);
            }
            CP_COMMIT();
            CP_WAIT0();
            __syncthreads();
        }
    }

    // ---- epilogue 2: w * (acc2 + b2) -> g_partial_h (fp16) ----
    {
        const int cb = (lane & 3) * 2;
        #pragma unroll
        for (int ms = 0; ms < 2; ++ms) {
            const int r0 = m0 + ms * 16 + (lane >> 2);
            const int r1 = r0 + 8;
            const float w0 = (r0 < valid) ? wsm_s[r0] : 0.f;
            const float w1 = (r1 < valid) ? wsm_s[r1] : 0.f;
            const size_t s0 = (size_t)(off + m0g + r0) * DMODEL;
            const size_t s1 = (size_t)(off + m0g + r1) * DMODEL;
            #pragma unroll
            for (int jn = 0; jn < 8; ++jn) {
                const float* a = acc2[ms * 8 + jn];
                int col = nw * 64 + jn * 8 + cb;
                float bb0 = b2s[col], bb1 = b2s[col + 1];
                if (r0 < valid) {
                    __half q0 = __float2half_rn(w0 * (a[0] + bb0));
                    __half q1 = __float2half_rn(w0 * (a[1] + bb1));
                    *reinterpret_cast<uint32_t*>(&g_partial_h[s0 + col]) = packh(q0, q1);
                }
                if (r1 < valid) {
                    __half q2 = __float2half_rn(w1 * (a[2] + bb0));
                    __half q3 = __float2half_rn(w1 * (a[3] + bb1));
                    *reinterpret_cast<uint32_t*>(&g_partial_h[s1 + col]) = packh(q2, q3);
                }
            }
        }
    }
}

// ================= kernel: combine (fp16 partials -> fp32 out) =================
__global__ void __launch_bounds__(256) combine_kernel(float* __restrict__ out) {
    int gid = blockIdx.x * 256 + threadIdx.x;
    int n = gid >> 4;
    int q = gid & 15;
    int s0 = g_tok_slot[2 * n];
    int s1 = g_tok_slot[2 * n + 1];
    const uint4* P = reinterpret_cast<const uint4*>(g_partial_h);
    uint4 u0 = P[(size_t)s0 * 16 + q];
    uint4 u1 = P[(size_t)s1 * 16 + q];
    const __half2* h0 = reinterpret_cast<const __half2*>(&u0);
    const __half2* h1 = reinterpret_cast<const __half2*>(&u1);
    float4 o0, o1;
    float2 a0 = __half22float2(h0[0]), b0 = __half22float2(h1[0]);
    float2 a1 = __half22float2(h0[1]), b1 = __half22float2(h1[1]);
    float2 a2 = __half22float2(h0[2]), b2 = __half22float2(h1[2]);
    float2 a3 = __half22float2(h0[3]), b3 = __half22float2(h1[3]);
    o0.x = a0.x + b0.x; o0.y = a0.y + b0.y;
    o0.z = a1.x + b1.x; o0.w = a1.y + b1.y;
    o1.x = a2.x + b2.x; o1.y = a2.y + b2.y;
    o1.z = a3.x + b3.x; o1.w = a3.y + b3.y;
    float4* O = reinterpret_cast<float4*>(out);
    O[(size_t)n * 32 + q * 2]     = o0;
    O[(size_t)n * 32 + q * 2 + 1] = o1;
}

// ================= launch =================
extern "C" void kernel_launch(void* const* d_in, const int* in_sizes, int n_in,
                              void* d_out, int out_size) {
    const float* x  = (const float*)d_in[0];
    const float* W1 = (const float*)d_in[1];
    const float* b1 = (const float*)d_in[2];
    const float* W2 = (const float*)d_in[3];
    const float* b2 = (const float*)d_in[4];
    const float* Wr = (const float*)d_in[5];
    const float* br = (const float*)d_in[6];
    float* out = (float*)d_out;

    cudaFuncSetAttribute(expert_mma_kernel,
                         cudaFuncAttributeMaxDynamicSharedMemorySize, SMEM_DYN);

    convert_w_kernel<<<2048, 256>>>(W1, W2);
    router_kernel<<<NTOK / 256, 256>>>(x, Wr, br);
    scatter_kernel<<<NTOK / 256, 256>>>(out, out_size);
    // max tiles = 2N/128 + NEXP = 1024 + 32
    expert_mma_kernel<<<1056, NTHR, SMEM_DYN>>>(b1, b2);
    combine_kernel<<<(NTOK * 16) / 256, 256>>>(out);
}

// round 14
// speedup vs baseline: 1.1994x; 1.0309x over previous
#include <cuda_runtime.h>
#include <cuda_fp16.h>
#include <math.h>
#include <stdint.h>

#define NTOK   65536
#define DMODEL 128
#define HDIM   256
#define NEXP   32
#define TM     128

// ================= helpers =================
__device__ __forceinline__ uint32_t smem_to_u32(const void* p) {
    uint32_t a;
    asm("{ .reg .u64 t; cvta.to.shared.u64 t, %1; cvt.u32.u64 %0, t; }" : "=r"(a) : "l"(p));
    return a;
}
__device__ __forceinline__ void ldsm4(uint32_t& r0, uint32_t& r1, uint32_t& r2, uint32_t& r3,
                                      uint32_t addr) {
    asm volatile("ldmatrix.sync.aligned.m8n8.x4.shared.b16 {%0,%1,%2,%3}, [%4];"
                 : "=r"(r0), "=r"(r1), "=r"(r2), "=r"(r3) : "r"(addr));
}
__device__ __forceinline__ void mma16816(float* c, uint32_t a0, uint32_t a1, uint32_t a2,
                                         uint32_t a3, uint32_t b0, uint32_t b1) {
    asm volatile("mma.sync.aligned.m16n8k16.row.col.f32.f16.f16.f32 "
                 "{%0,%1,%2,%3}, {%4,%5,%6,%7}, {%8,%9}, {%0,%1,%2,%3};"
                 : "+f"(c[0]), "+f"(c[1]), "+f"(c[2]), "+f"(c[3])
                 : "r"(a0), "r"(a1), "r"(a2), "r"(a3), "r"(b0), "r"(b1));
}
__device__ __forceinline__ void cp16(uint32_t dst, const void* src) {
    asm volatile("cp.async.cg.shared.global [%0], [%1], 16;" :: "r"(dst), "l"(src) : "memory");
}
#define CP_COMMIT() asm volatile("cp.async.commit_group;" ::: "memory")
#define CP_WAIT0()  asm volatile("cp.async.wait_group 0;" ::: "memory")
#define CP_WAIT1()  asm volatile("cp.async.wait_group 1;" ::: "memory")

__device__ __forceinline__ uint32_t packh(__half a, __half b) {
    __half2 t(a, b);
    return *reinterpret_cast<uint32_t*>(&t);
}

// ================= device scratch =================
__device__ float g_top_v[2 * NTOK];
__device__ int   g_top_e[2 * NTOK];
__device__ float g_importance[NEXP];
__device__ int   g_counts[NEXP];
__device__ int   g_cursor[NEXP];
__device__ int   g_bucket_tok[2 * NTOK];
__device__ float g_bucket_w[2 * NTOK];
__device__ int   g_tok_slot[2 * NTOK];
__device__ __align__(16) __half g_partial_h[(size_t)2 * NTOK * DMODEL];

__device__ __align__(16) __half g_xh[NTOK * DMODEL];
__device__ __align__(16) __half g_w1h[NEXP * HDIM * DMODEL];   // [E,H,D]
__device__ __align__(16) __half g_w2h[NEXP * DMODEL * HDIM];   // [E,D,H]

// ================= kernel: coalesced transpose-convert weights (+ init in block 0) =================
__global__ void __launch_bounds__(256) convert_w_kernel(const float* __restrict__ W1,
                                                        const float* __restrict__ W2) {
    __shared__ float tile[32][33];
    const int b = blockIdx.x;
    const int tx = threadIdx.x & 31;
    const int ty = threadIdx.x >> 5;

    if (b == 0 && threadIdx.x < NEXP) {
        g_counts[threadIdx.x] = 0;
        g_cursor[threadIdx.x] = 0;
        g_importance[threadIdx.x] = 0.f;
    }

    if (b < 1024) {
        int e = b >> 5, r = b & 31;
        int dblk = r >> 3, hblk = r & 7;
        const float* src = W1 + ((size_t)e * 128 + dblk * 32) * 256 + hblk * 32;
        #pragma unroll
        for (int i = 0; i < 4; ++i)
            tile[ty + i * 8][tx] = src[(size_t)(ty + i * 8) * 256 + tx];
        __syncthreads();
        __half* dst = g_w1h + ((size_t)e * 256 + hblk * 32) * 128 + dblk * 32;
        #pragma unroll
        for (int i = 0; i < 4; ++i)
            dst[(size_t)(ty + i * 8) * 128 + tx] = __float2half_rn(tile[tx][ty + i * 8]);
    } else {
        int bb = b - 1024;
        int e = bb >> 5, r = bb & 31;
        int hblk = r >> 2, dblk = r & 3;
        const float* src = W2 + ((size_t)e * 256 + hblk * 32) * 128 + dblk * 32;
        #pragma unroll
        for (int i = 0; i < 4; ++i)
            tile[ty + i * 8][tx] = src[(size_t)(ty + i * 8) * 128 + tx];
        __syncthreads();
        __half* dst = g_w2h + ((size_t)e * 128 + dblk * 32) * 256 + hblk * 32;
        #pragma unroll
        for (int i = 0; i < 4; ++i)
            dst[(size_t)(ty + i * 8) * 256 + tx] = __float2half_rn(tile[tx][ty + i * 8]);
    }
}

// ================= kernel: router (thread per token; also emits x as fp16) =================
__global__ void __launch_bounds__(256) router_kernel(
    const float* __restrict__ x, const float* __restrict__ Wr,
    const float* __restrict__ br)
{
    __shared__ float wr_s[DMODEL * NEXP];
    __shared__ float br_s[NEXP];
    __shared__ float imp_s[NEXP];
    __shared__ int   cnt_s[NEXP];

    const int tid = threadIdx.x;
    if (tid < NEXP) { imp_s[tid] = 0.f; cnt_s[tid] = 0; br_s[tid] = br[tid]; }
    #pragma unroll
    for (int i = tid; i < DMODEL * NEXP; i += 256) wr_s[i] = Wr[i];
    __syncthreads();

    const int n = blockIdx.x * 256 + tid;

    float acc[NEXP];
    #pragma unroll
    for (int e = 0; e < NEXP; ++e) acc[e] = br_s[e];

    const float4* xrow = reinterpret_cast<const float4*>(x + (size_t)n * DMODEL);
    float4 xv = xrow[0];
    uint32_t hprev0 = 0, hprev1 = 0;
    #pragma unroll 4
    for (int ch = 0; ch < 32; ++ch) {
        float4 xn;
        if (ch < 31) xn = xrow[ch + 1];

        uint32_t p0 = packh(__float2half_rn(xv.x), __float2half_rn(xv.y));
        uint32_t p1 = packh(__float2half_rn(xv.z), __float2half_rn(xv.w));
        if (ch & 1) {
            *reinterpret_cast<uint4*>(g_xh + (size_t)n * DMODEL + (ch - 1) * 4) =
                make_uint4(hprev0, hprev1, p0, p1);
        } else { hprev0 = p0; hprev1 = p1; }

        float xd[4] = {xv.x, xv.y, xv.z, xv.w};
        #pragma unroll
        for (int dd = 0; dd < 4; ++dd) {
            const float4* wrow = reinterpret_cast<const float4*>(&wr_s[(ch * 4 + dd) * NEXP]);
            #pragma unroll
            for (int e4 = 0; e4 < 8; ++e4) {
                float4 w = wrow[e4];
                acc[e4 * 4 + 0] = fmaf(xd[dd], w.x, acc[e4 * 4 + 0]);
                acc[e4 * 4 + 1] = fmaf(xd[dd], w.y, acc[e4 * 4 + 1]);
                acc[e4 * 4 + 2] = fmaf(xd[dd], w.z, acc[e4 * 4 + 2]);
                acc[e4 * 4 + 3] = fmaf(xd[dd], w.w, acc[e4 * 4 + 3]);
            }
        }
        xv = xn;
    }

    float mx = acc[0];
    #pragma unroll
    for (int e = 1; e < NEXP; ++e) mx = fmaxf(mx, acc[e]);
    float s = 0.f;
    #pragma unroll
    for (int e = 0; e < NEXP; ++e) { acc[e] = expf(acc[e] - mx); s += acc[e]; }
    float inv = 1.f / s;
    #pragma unroll
    for (int e = 0; e < NEXP; ++e) acc[e] *= inv;

    float v1 = acc[0]; int i1 = 0;
    #pragma unroll
    for (int e = 1; e < NEXP; ++e) if (acc[e] > v1) { v1 = acc[e]; i1 = e; }
    float v2 = -1.f; int i2 = 0;
    #pragma unroll
    for (int e = 0; e < NEXP; ++e) {
        bool ok = (e != i1) && (acc[e] > v2);
        if (ok) { v2 = acc[e]; i2 = e; }
    }

    g_top_e[2 * n]     = i1;  g_top_v[2 * n]     = v1;
    g_top_e[2 * n + 1] = i2;  g_top_v[2 * n + 1] = v2;
    atomicAdd(&imp_s[i1], v1);
    atomicAdd(&imp_s[i2], v2);
    atomicAdd(&cnt_s[i1], 1);
    atomicAdd(&cnt_s[i2], 1);

    __syncthreads();
    if (tid < NEXP) {
        atomicAdd(&g_importance[tid], imp_s[tid]);
        atomicAdd(&g_counts[tid], cnt_s[tid]);
    }
}

// ================= kernel: scatter (computes offsets locally; block 0 writes loss) =================
__global__ void __launch_bounds__(256) scatter_kernel(float* __restrict__ out, int out_size) {
    __shared__ int offs[NEXP];
    __shared__ int lcnt[NEXP];
    __shared__ int gbase[NEXP];
    __shared__ int lcur[NEXP];

    const int tid = threadIdx.x;
    const unsigned FULL = 0xffffffffu;

    if (tid < 32) {
        int c = g_counts[tid];
        int sc = c;
        #pragma unroll
        for (int o = 1; o < 32; o <<= 1) {
            int v = __shfl_up_sync(FULL, sc, o);
            if (tid >= o) sc += v;
        }
        offs[tid] = sc - c;
        lcnt[tid] = 0;
    }
    if (blockIdx.x == 0 && (tid >> 5) == 1) {
        int lane = tid & 31;
        float imp = g_importance[lane];
        float s = imp;
        #pragma unroll
        for (int o = 16; o; o >>= 1) s += __shfl_xor_sync(FULL, s, o);
        float mean = s / 32.f;
        float d = imp - mean;
        float ss = d * d;
        #pragma unroll
        for (int o = 16; o; o >>= 1) ss += __shfl_xor_sync(FULL, ss, o);
        float var = ss / 31.f;
        if (lane == 0 && out_size > NTOK * DMODEL)
            out[NTOK * DMODEL] = var / (mean * mean + 1e-9f);
    }
    __syncthreads();

    const int n = blockIdx.x * 256 + tid;
    int e0 = g_top_e[2 * n];     float v0 = g_top_v[2 * n];
    int e1 = g_top_e[2 * n + 1]; float v1 = g_top_v[2 * n + 1];
    atomicAdd(&lcnt[e0], 1);
    atomicAdd(&lcnt[e1], 1);
    __syncthreads();

    if (tid < NEXP) { gbase[tid] = offs[tid] + atomicAdd(&g_cursor[tid], lcnt[tid]); lcur[tid] = 0; }
    __syncthreads();

    int p0 = gbase[e0] + atomicAdd(&lcur[e0], 1);
    g_bucket_tok[p0] = n; g_bucket_w[p0] = v0; g_tok_slot[2 * n] = p0;
    int p1 = gbase[e1] + atomicAdd(&lcur[e1], 1);
    g_bucket_tok[p1] = n; g_bucket_w[p1] = v1; g_tok_slot[2 * n + 1] = p1;
}

// ================= kernel: grouped expert GEMM (fp16, TM=128, pipelined WA/WB, 2 CTA/SM) =================
// X  @ O_XH : [128,128] fp16, s272  (34816)
// WA @ O_WA : W1 chunk [64h,128d] s272  (17408, padded 18432)
// WB @ O_WB : W2 chunk [128d,64h] s144  (18432)
// C  @ O_CH : h chunk [128,64] s144     (18432)
#define RW128 272
#define RW64  144
#define O_XH  0
#define O_WA  34816
#define O_WB  53248
#define O_CH  71680
#define O_TOK 90112
#define O_WSM (O_TOK + 512)
#define O_B1  (O_TOK + 1024)
#define O_B2  (O_TOK + 2048)
#define O_CNT (O_TOK + 2560)
#define O_OFF (O_TOK + 2688)
#define O_TF  (O_TOK + 2816)
#define SMEM_DYN (O_TOK + 3072)   // 93184

#define NTHR 256

__global__ void __launch_bounds__(NTHR, 2) expert_mma_kernel(
    const float* __restrict__ b1, const float* __restrict__ b2)
{
    const int t = blockIdx.x;

    extern __shared__ char smp[];
    const uint32_t sbase = smem_to_u32(smp);
    int*   toks_s = (int*)(smp + O_TOK);
    float* wsm_s  = (float*)(smp + O_WSM);
    float* b1s    = (float*)(smp + O_B1);
    float* b2s    = (float*)(smp + O_B2);
    int*   cnt_s  = (int*)(smp + O_CNT);
    int*   off_s  = (int*)(smp + O_OFF);
    int*   tf_s   = (int*)(smp + O_TF);

    const int tid = threadIdx.x;
    const int wid = tid >> 5;
    const int lane = tid & 31;
    const unsigned FULL = 0xffffffffu;

    if (wid == 0) {
        int c = g_counts[lane];
        int sc = c;
        #pragma unroll
        for (int o = 1; o < 32; o <<= 1) {
            int v = __shfl_up_sync(FULL, sc, o);
            if (lane >= o) sc += v;
        }
        off_s[lane] = sc - c;
        cnt_s[lane] = c;
        int nt = (c + TM - 1) / TM;
        int st = nt;
        #pragma unroll
        for (int o = 1; o < 32; o <<= 1) {
            int v = __shfl_up_sync(FULL, st, o);
            if (lane >= o) st += v;
        }
        tf_s[lane + 1] = st;
        if (lane == 0) tf_s[0] = 0;
    }
    __syncthreads();
    if (t >= tf_s[NEXP]) return;

    int e = 0;
    #pragma unroll 1
    while (t >= tf_s[e + 1]) ++e;
    const int mtile = t - tf_s[e];
    const int off   = off_s[e];
    const int cnt   = cnt_s[e];
    const int m0g   = mtile * TM;
    const int valid = min(TM, cnt - m0g);

    if (tid < 128) {
        if (tid < valid) {
            toks_s[tid] = g_bucket_tok[off + m0g + tid];
            wsm_s[tid]  = g_bucket_w[off + m0g + tid];
        } else { toks_s[tid] = 0; wsm_s[tid] = 0.f; }
        b2s[tid] = b2[e * DMODEL + tid];
    }
    b1s[tid] = b1[e * HDIM + tid];
    __syncthreads();

    const size_t w1base = (size_t)e * HDIM * DMODEL;
    const size_t w2base = (size_t)e * DMODEL * HDIM;

    // ---- prologue: G1 = {X gather, W1c0 -> WA}; G2 = {W2c0 -> WB} ----
    #pragma unroll
    for (int i = tid; i < 2048; i += NTHR) {
        int r = i >> 4, ch = i & 15;
        const size_t src = (size_t)toks_s[r] * DMODEL + ch * 8;
        cp16(sbase + O_XH + r * RW128 + ch * 16, g_xh + src);
    }
    #pragma unroll
    for (int i = tid; i < 1024; i += NTHR) {
        int r = i >> 4, ch = i & 15;
        cp16(sbase + O_WA + r * RW128 + ch * 16, g_w1h + w1base + (size_t)r * DMODEL + ch * 8);
    }
    CP_COMMIT();
    #pragma unroll
    for (int i = tid; i < 1024; i += NTHR) {
        int r = i >> 3, ch = i & 7;
        cp16(sbase + O_WB + r * RW64 + ch * 16, g_w2h + w2base + (size_t)r * HDIM + ch * 8);
    }
    CP_COMMIT();
    CP_WAIT1();          // X + W1c0 ready; W2c0 covered by FC1
    __syncthreads();

    // warp tiling: 4 m-warps (32 rows each) x 2 n-warps
    const int m0 = (wid >> 1) * 32;
    const int nw = wid & 1;
    const uint32_t arow  = m0 + (lane & 15);
    const uint32_t acolb = ((lane >> 4) & 1) * 16;
    const uint32_t brsub = ((lane >> 4) & 1) * 8 + (lane & 7);
    const uint32_t bcolb = ((lane >> 3) & 1) * 16;

    float acc2[16][4];
    #pragma unroll
    for (int j = 0; j < 16; ++j)
        #pragma unroll
        for (int q = 0; q < 4; ++q) acc2[j][q] = 0.f;

    #pragma unroll 1
    for (int c = 0; c < 4; ++c) {
        // ---- FC1: h_c[128,64] = X @ W1c^T (WA) ; warp m32 x n32 ----
        float acc1[8][4];
        #pragma unroll
        for (int j = 0; j < 8; ++j)
            #pragma unroll
            for (int q = 0; q < 4; ++q) acc1[j][q] = 0.f;

        #pragma unroll 1
        for (int k = 0; k < 8; ++k) {
            uint32_t aaddr0 = sbase + O_XH + arow * RW128 + k * 32 + acolb;
            uint32_t ah[8];
            ldsm4(ah[0], ah[1], ah[2], ah[3], aaddr0);
            ldsm4(ah[4], ah[5], ah[6], ah[7], aaddr0 + 16 * RW128);
            #pragma unroll
            for (int jp = 0; jp < 2; ++jp) {
                uint32_t brow = nw * 32 + jp * 16 + brsub;
                uint32_t baddr = sbase + O_WA + brow * RW128 + k * 32 + bcolb;
                uint32_t bh0, bh1, bh2, bh3;
                ldsm4(bh0, bh1, bh2, bh3, baddr);
                #pragma unroll
                for (int ms = 0; ms < 2; ++ms) {
                    const uint32_t* A = ah + ms * 4;
                    mma16816(acc1[ms * 4 + 2 * jp],     A[0], A[1], A[2], A[3], bh0, bh1);
                    mma16816(acc1[ms * 4 + 2 * jp + 1], A[0], A[1], A[2], A[3], bh2, bh3);
                }
            }
        }
        __syncthreads();   // WA consumed by all warps

        // ---- prefetch W1(c+1) -> WA (slack: epilogue + FC2) ----
        if (c < 3) {
            #pragma unroll
            for (int i = tid; i < 1024; i += NTHR) {
                int r = i >> 4, ch = i & 15;
                size_t src = w1base + (size_t)((c + 1) * 64 + r) * DMODEL + ch * 8;
                cp16(sbase + O_WA + r * RW128 + ch * 16, g_w1h + src);
            }
            CP_COMMIT();
        }

        // ---- epilogue 1: relu(acc1 + b1) -> fp16 into C ----
        {
            const int cb = (lane & 3) * 2;
            #pragma unroll
            for (int ms = 0; ms < 2; ++ms) {
                const int r0 = m0 + ms * 16 + (lane >> 2);
                #pragma unroll
                for (int jn = 0; jn < 4; ++jn) {
                    const float* a = acc1[ms * 4 + jn];
                    int coll = nw * 32 + jn * 8 + cb;
                    int colg = c * 64 + coll;
                    float bb0 = b1s[colg], bb1 = b1s[colg + 1];
                    __half h0 = __float2half_rn(fmaxf(a[0] + bb0, 0.f));
                    __half h1 = __float2half_rn(fmaxf(a[1] + bb1, 0.f));
                    __half h2 = __float2half_rn(fmaxf(a[2] + bb0, 0.f));
                    __half h3 = __float2half_rn(fmaxf(a[3] + bb1, 0.f));
                    *reinterpret_cast<uint32_t*>(smp + O_CH + r0 * RW64 + coll * 2) = packh(h0, h1);
                    *reinterpret_cast<uint32_t*>(smp + O_CH + (r0 + 8) * RW64 + coll * 2) = packh(h2, h3);
                }
            }
        }
        // W2c must be done: pending = {W2c, W1c+1} (c<3) -> wait1 ; c=3: {W2c3} -> wait0
        if (c < 3) { CP_WAIT1(); } else { CP_WAIT0(); }
        __syncthreads();   // WB ready, C visible

        // ---- FC2: acc2 += h_c @ W2c^T (WB) ; warp m32 x n64 ----
        #pragma unroll 1
        for (int k = 0; k < 4; ++k) {
            uint32_t aaddr0 = sbase + O_CH + arow * RW64 + k * 32 + acolb;
            uint32_t ah[8];
            ldsm4(ah[0], ah[1], ah[2], ah[3], aaddr0);
            ldsm4(ah[4], ah[5], ah[6], ah[7], aaddr0 + 16 * RW64);
            #pragma unroll
            for (int jp = 0; jp < 4; ++jp) {
                uint32_t brow = nw * 64 + jp * 16 + brsub;
                uint32_t baddr = sbase + O_WB + brow * RW64 + k * 32 + bcolb;
                uint32_t bh0, bh1, bh2, bh3;
                ldsm4(bh0, bh1, bh2, bh3, baddr);
                #pragma unroll
                for (int ms = 0; ms < 2; ++ms) {
                    const uint32_t* A = ah + ms * 4;
                    mma16816(acc2[ms * 8 + 2 * jp],     A[0], A[1], A[2], A[3], bh0, bh1);
                    mma16816(acc2[ms * 8 + 2 * jp + 1], A[0], A[1], A[2], A[3], bh2, bh3);
                }
            }
        }
        __syncthreads();   // WB + C consumed

        // ---- prefetch W2(c+1) -> WB; ensure W1(c+1) landed before next FC1 ----
        if (c < 3) {
            #pragma unroll
            for (int i = tid; i < 1024; i += NTHR) {
                int r = i >> 3, ch = i & 7;
                size_t src = w2base + (size_t)r * HDIM + (c + 1) * 64 + ch * 8;
                cp16(sbase + O_WB + r * RW64 + ch * 16, g_w2h + src);
            }
            CP_COMMIT();
            CP_WAIT1();    // pending {W1c+1, W2c+1} -> W1c+1 done
            __syncthreads();
        }
    }

    // ---- epilogue 2: w * (acc2 + b2) -> g_partial_h (fp16) ----
    {
        const int cb = (lane & 3) * 2;
        #pragma unroll
        for (int ms = 0; ms < 2; ++ms) {
            const int r0 = m0 + ms * 16 + (lane >> 2);
            const int r1 = r0 + 8;
            const float w0 = (r0 < valid) ? wsm_s[r0] : 0.f;
            const float w1 = (r1 < valid) ? wsm_s[r1] : 0.f;
            const size_t s0 = (size_t)(off + m0g + r0) * DMODEL;
            const size_t s1 = (size_t)(off + m0g + r1) * DMODEL;
            #pragma unroll
            for (int jn = 0; jn < 8; ++jn) {
                const float* a = acc2[ms * 8 + jn];
                int col = nw * 64 + jn * 8 + cb;
                float bb0 = b2s[col], bb1 = b2s[col + 1];
                if (r0 < valid) {
                    __half q0 = __float2half_rn(w0 * (a[0] + bb0));
                    __half q1 = __float2half_rn(w0 * (a[1] + bb1));
                    *reinterpret_cast<uint32_t*>(&g_partial_h[s0 + col]) = packh(q0, q1);
                }
                if (r1 < valid) {
                    __half q2 = __float2half_rn(w1 * (a[2] + bb0));
                    __half q3 = __float2half_rn(w1 * (a[3] + bb1));
                    *reinterpret_cast<uint32_t*>(&g_partial_h[s1 + col]) = packh(q2, q3);
                }
            }
        }
    }
}

// ================= kernel: combine (fp16 partials -> fp32 out) =================
__global__ void __launch_bounds__(256) combine_kernel(float* __restrict__ out) {
    int gid = blockIdx.x * 256 + threadIdx.x;
    int n = gid >> 4;
    int q = gid & 15;
    int s0 = g_tok_slot[2 * n];
    int s1 = g_tok_slot[2 * n + 1];
    const uint4* P = reinterpret_cast<const uint4*>(g_partial_h);
    uint4 u0 = P[(size_t)s0 * 16 + q];
    uint4 u1 = P[(size_t)s1 * 16 + q];
    const __half2* h0 = reinterpret_cast<const __half2*>(&u0);
    const __half2* h1 = reinterpret_cast<const __half2*>(&u1);
    float4 o0, o1;
    float2 a0 = __half22float2(h0[0]), b0 = __half22float2(h1[0]);
    float2 a1 = __half22float2(h0[1]), b1 = __half22float2(h1[1]);
    float2 a2 = __half22float2(h0[2]), b2 = __half22float2(h1[2]);
    float2 a3 = __half22float2(h0[3]), b3 = __half22float2(h1[3]);
    o0.x = a0.x + b0.x; o0.y = a0.y + b0.y;
    o0.z = a1.x + b1.x; o0.w = a1.y + b1.y;
    o1.x = a2.x + b2.x; o1.y = a2.y + b2.y;
    o1.z = a3.x + b3.x; o1.w = a3.y + b3.y;
    float4* O = reinterpret_cast<float4*>(out);
    O[(size_t)n * 32 + q * 2]     = o0;
    O[(size_t)n * 32 + q * 2 + 1] = o1;
}

// ================= launch =================
extern "C" void kernel_launch(void* const* d_in, const int* in_sizes, int n_in,
                              void* d_out, int out_size) {
    const float* x  = (const float*)d_in[0];
    const float* W1 = (const float*)d_in[1];
    const float* b1 = (const float*)d_in[2];
    const float* W2 = (const float*)d_in[3];
    const float* b2 = (const float*)d_in[4];
    const float* Wr = (const float*)d_in[5];
    const float* br = (const float*)d_in[6];
    float* out = (float*)d_out;

    cudaFuncSetAttribute(expert_mma_kernel,
                         cudaFuncAttributeMaxDynamicSharedMemorySize, SMEM_DYN);

    convert_w_kernel<<<2048, 256>>>(W1, W2);
    router_kernel<<<NTOK / 256, 256>>>(x, Wr, br);
    scatter_kernel<<<NTOK / 256, 256>>>(out, out_size);
    expert_mma_kernel<<<1056, NTHR, SMEM_DYN>>>(b1, b2);
    combine_kernel<<<(NTOK * 16) / 256, 256>>>(out);
}